// round 9
// baseline (speedup 1.0000x reference)
#include <cuda_runtime.h>
#include <cstdint>

#define B_  8
#define C_  21
#define D_  64
#define O_  128
#define HW_ 65536
#define N_TOT (B_ * HW_)

typedef unsigned long long ull;
typedef unsigned int uint;

#define FFMA2(acc, a, b) asm("fma.rn.f32x2 %0, %1, %2, %0;" : "+l"(acc) : "l"(a), "l"(b))
#define FADD2(acc, a)    asm("add.rn.f32x2 %0, %0, %1;"     : "+l"(acc) : "l"(a))

// ---------------- device scratch ---------------------------------------------
#define KS_CHUNKS 74
#define NVAL 252                      // 231 triangle + 21 sums
__device__ float g_Gp[KS_CHUNKS * B_ * NVAL];   // per-block stat partials
__device__ float g_W2T[B_ * C_ * O_];           // combined weights [b][c][o]
__device__ float g_partY[B_ * O_];
__device__ float g_partQ[B_ * O_];
__device__ float g_A2s[B_ * C_ * O_];           // alpha*W2 (scalar), [b][c][o]
__device__ float g_bias2f[O_];                  // fused bias (scalar)

// ---------------- helpers ------------------------------------------------------
__device__ __forceinline__ float pairsum(ull a) {
    return __uint_as_float((uint)(a & 0xffffffffu)) + __uint_as_float((uint)(a >> 32));
}
__device__ __forceinline__ ull lo64(float4 v) {
    return ((ull)__float_as_uint(v.y) << 32) | __float_as_uint(v.x);
}
__device__ __forceinline__ ull hi64(float4 v) {
    return ((ull)__float_as_uint(v.w) << 32) | __float_as_uint(v.z);
}
__device__ __forceinline__ ull dup2(float x) {
    ull r;
    asm("mov.b64 %0, {%1, %1};" : "=l"(r) : "f"(x));
    return r;
}
__device__ __forceinline__ float wredsum(float v) {
#pragma unroll
    for (int off = 16; off; off >>= 1) v += __shfl_xor_sync(0xffffffffu, v, off);
    return v;
}

// ---------------- kstats: symmetric (triangular) Gram, LDG streaming ---------
// grid (74, 8), 352 threads = 11 warps, NO min-blocks (avoid reg cap -> spills).
// Warp w<10 owns row pair (w, 20-w); warp 10 owns row 10.
template <int LO, int HI>
__device__ __forceinline__ void gram_warp(const float* __restrict__ mb,
                                          int u0, int u1, int lane,
                                          float* __restrict__ gp) {
    constexpr bool SGL = (LO == HI);
    constexpr int TRI_LO = LO * (LO + 1) / 2;
    constexpr int TRI_HI = HI * (HI + 1) / 2;

    ull accH[HI + 1];
    ull accL[SGL ? 1 : LO + 1];
    ull sL = 0ull, sH = 0ull;
#pragma unroll
    for (int c = 0; c <= HI; c++) accH[c] = 0ull;
    if (!SGL) {
#pragma unroll
        for (int c = 0; c <= LO; c++) accL[c] = 0ull;
    }

#pragma unroll 1
    for (int u = u0; u < u1; u++) {
        const int q = u * 32 + lane;
        float4 vH = reinterpret_cast<const float4*>(mb + (size_t)HI * HW_)[q];
        ull mrHa = lo64(vH), mrHb = hi64(vH);
        FADD2(sH, mrHa); FADD2(sH, mrHb);
        ull mrLa = 0, mrLb = 0;
        if (!SGL) {
            float4 vL = reinterpret_cast<const float4*>(mb + (size_t)LO * HW_)[q];
            mrLa = lo64(vL); mrLb = hi64(vL);
            FADD2(sL, mrLa); FADD2(sL, mrLb);
        }
#pragma unroll
        for (int c = 0; c <= HI; c++) {
            ull va, vb;
            if (c == HI)              { va = mrHa; vb = mrHb; }
            else if (!SGL && c == LO) { va = mrLa; vb = mrLb; }
            else {
                float4 v = reinterpret_cast<const float4*>(mb + (size_t)c * HW_)[q];
                va = lo64(v); vb = hi64(v);
            }
            FFMA2(accH[c], mrHa, va);
            FFMA2(accH[c], mrHb, vb);
            if (!SGL && c <= LO) {
                FFMA2(accL[c], mrLa, va);
                FFMA2(accL[c], mrLb, vb);
            }
        }
    }

#pragma unroll
    for (int c = 0; c <= HI; c++) {
        float v = wredsum(pairsum(accH[c]));
        if (lane == 0) gp[TRI_HI + c] = v;
    }
    {
        float v = wredsum(pairsum(sH));
        if (lane == 0) gp[231 + HI] = v;
    }
    if (!SGL) {
#pragma unroll
        for (int c = 0; c <= LO; c++) {
            float v = wredsum(pairsum(accL[c]));
            if (lane == 0) gp[TRI_LO + c] = v;
        }
        float v = wredsum(pairsum(sL));
        if (lane == 0) gp[231 + LO] = v;
    }
}

__global__ __launch_bounds__(352) void kstats(const float* __restrict__ mask) {
    const int b = blockIdx.y;
    const int bidx = blockIdx.x;
    const int wid = threadIdx.x >> 5;
    const int lane = threadIdx.x & 31;

    const int u0 = (bidx * 512) / KS_CHUNKS;
    const int u1 = ((bidx + 1) * 512) / KS_CHUNKS;

    const float* mb = mask + (size_t)b * C_ * HW_;
    float* gp = g_Gp + (bidx * B_ + b) * NVAL;

    switch (wid) {
        case 0:  gram_warp<0, 20>(mb, u0, u1, lane, gp); break;
        case 1:  gram_warp<1, 19>(mb, u0, u1, lane, gp); break;
        case 2:  gram_warp<2, 18>(mb, u0, u1, lane, gp); break;
        case 3:  gram_warp<3, 17>(mb, u0, u1, lane, gp); break;
        case 4:  gram_warp<4, 16>(mb, u0, u1, lane, gp); break;
        case 5:  gram_warp<5, 15>(mb, u0, u1, lane, gp); break;
        case 6:  gram_warp<6, 14>(mb, u0, u1, lane, gp); break;
        case 7:  gram_warp<7, 13>(mb, u0, u1, lane, gp); break;
        case 8:  gram_warp<8, 12>(mb, u0, u1, lane, gp); break;
        case 9:  gram_warp<9, 11>(mb, u0, u1, lane, gp); break;
        default: gram_warp<10, 10>(mb, u0, u1, lane, gp); break;
    }
}

// ---------------- kprep_a: W2T + partial reduce + quadratic forms -------------
__global__ __launch_bounds__(256) void kprep_a(const float* __restrict__ feat,
                                               const float* __restrict__ conv_w) {
    __shared__ float sWT[D_ * 129 + 32];
    __shared__ float sF[C_ * D_];
    __shared__ float sG[231];
    __shared__ float sS[C_];
    const int b = blockIdx.x;
    const int tid = threadIdx.x;

    for (int i = tid; i < O_ * D_; i += 256) {
        int o = i >> 6, d = i & 63;
        sWT[d * 129 + o] = conv_w[i];
    }
    for (int i = tid; i < C_ * D_; i += 256) sF[i] = feat[b * C_ * D_ + i];
    for (int v = tid; v < NVAL; v += 256) {
        float s = 0.f;
#pragma unroll
        for (int ch = 0; ch < KS_CHUNKS; ch++) s += g_Gp[(ch * B_ + b) * NVAL + v];
        if (v < 231) sG[v] = s;
        else         sS[v - 231] = s;
    }
    __syncthreads();

    for (int idx = tid; idx < C_ * O_; idx += 256) {
        int c = idx >> 7, o = idx & 127;
        float s = 0.f;
#pragma unroll
        for (int d = 0; d < D_; d++)
            s = fmaf(sWT[d * 129 + o], sF[c * D_ + d], s);
        g_W2T[b * C_ * O_ + idx] = s;
    }
    __syncthreads();

    if (tid < O_) {
        const int o = tid;
        float w[C_];
#pragma unroll
        for (int c = 0; c < C_; c++) w[c] = g_W2T[(b * C_ + c) * O_ + o];
        float sumY = 0.f;
#pragma unroll
        for (int c = 0; c < C_; c++) sumY = fmaf(w[c], sS[c], sumY);
        float sumQ = 0.f;
#pragma unroll
        for (int r = 0; r < C_; r++) {
            const int tr = r * (r + 1) / 2;
            float t = sG[tr + r] * w[r];
#pragma unroll
            for (int c = 0; c < r; c++) t = fmaf(2.f * sG[tr + c], w[c], t);
            sumQ = fmaf(w[r], t, sumQ);
        }
        g_partY[b * O_ + o] = sumY;
        g_partQ[b * O_ + o] = sumQ;
    }
}

// ---------------- kprep_b: alpha/bias (redundant per block) + A2 scaling -----
__global__ __launch_bounds__(128) void kprep_b(const float* __restrict__ conv_b,
                                               const float* __restrict__ gamma,
                                               const float* __restrict__ beta) {
    const int b = blockIdx.x;
    const int o = threadIdx.x;

    float sumY = 0.f, sumQ = 0.f;
#pragma unroll
    for (int bb = 0; bb < B_; bb++) {
        sumY += g_partY[bb * O_ + o];
        sumQ += g_partQ[bb * O_ + o];
    }
    const float invN = 1.f / (float)N_TOT;
    const float b0 = conv_b[o];
    const float es = sumY * invN;
    const float mean = b0 + es;
    const float ey2 = sumQ * invN + 2.f * b0 * es + b0 * b0;
    const float var = ey2 - mean * mean;
    const float alpha = gamma[o] * rsqrtf(var + 1e-5f);

    if (b == 0) g_bias2f[o] = beta[o] + alpha * (b0 - mean);
#pragma unroll
    for (int c = 0; c < C_; c++) {
        const int idx = b * C_ * O_ + c * O_ + o;
        g_A2s[idx] = alpha * g_W2T[idx];
    }
}

// ---------------- kmain: no-smem fused K=21 GEMM + BN + ReLU -----------------
// 148 blocks x 256 threads (1 block/SM), no __syncthreads, no cp.async.
// Warp = 16 channels x 256 px; thread = 2 quads (8 px) x 16 ch.
// Mask: direct LDG.128 (8 warps share lines -> L1-hot), 1-iter prefetch.
// Coefs: scalar uniform LDG.128 (L1-hot) packed to f32x2 via ALU mov.b64.
#define KM_NBLK 148
#define KM_NT   2048        // 8 b * 256 subtiles of 256 px
#define KM_PX   256

__global__ __launch_bounds__(256) void kmain(const float* __restrict__ mask,
                                             float* __restrict__ out) {
    const int tid = threadIdx.x;
    const int wid = tid >> 5;
    const int lane = tid & 31;
    const int o0 = wid * 16;

    const int bid = blockIdx.x;
    const int t0 = (bid * KM_NT) / KM_NBLK;
    const int t1 = ((bid + 1) * KM_NT) / KM_NBLK;

    // hoist scalar fused bias (16 regs)
    float bias[16];
#pragma unroll
    for (int j = 0; j < 16; j++) bias[j] = g_bias2f[o0 + j];

#pragma unroll 1
    for (int s = t0; s < t1; s++) {
        const int b = s >> 8;
        const int px = (s & 255) * KM_PX;
        const float* mb = mask + (size_t)b * C_ * HW_ + px;
        const float* cfb = g_A2s + ((size_t)b * C_) * O_ + o0;

        ull acc[16][2][2];   // [ch][quad][half]
#pragma unroll
        for (int j = 0; j < 16; j++) {
            ull d = dup2(bias[j]);
            acc[j][0][0] = d; acc[j][0][1] = d;
            acc[j][1][0] = d; acc[j][1][1] = d;
        }

        // prefetch mask row c=0
        ulonglong2 mq0 = reinterpret_cast<const ulonglong2*>(mb)[lane];
        ulonglong2 mq1 = reinterpret_cast<const ulonglong2*>(mb)[lane + 32];

#pragma unroll
        for (int c = 0; c < C_; c++) {
            ulonglong2 nq0, nq1;
            if (c + 1 < C_) {
                const float* mn = mb + (size_t)(c + 1) * HW_;
                nq0 = reinterpret_cast<const ulonglong2*>(mn)[lane];
                nq1 = reinterpret_cast<const ulonglong2*>(mn)[lane + 32];
            }
            const float4* cfp = reinterpret_cast<const float4*>(cfb + (size_t)c * O_);
#pragma unroll
            for (int g = 0; g < 4; g++) {
                float4 w = cfp[g];               // warp-uniform LDG.128, L1-hot
                ull c0 = dup2(w.x), c1 = dup2(w.y), c2 = dup2(w.z), c3 = dup2(w.w);
                const int j = g * 4;
                FFMA2(acc[j + 0][0][0], c0, mq0.x); FFMA2(acc[j + 0][0][1], c0, mq0.y);
                FFMA2(acc[j + 0][1][0], c0, mq1.x); FFMA2(acc[j + 0][1][1], c0, mq1.y);
                FFMA2(acc[j + 1][0][0], c1, mq0.x); FFMA2(acc[j + 1][0][1], c1, mq0.y);
                FFMA2(acc[j + 1][1][0], c1, mq1.x); FFMA2(acc[j + 1][1][1], c1, mq1.y);
                FFMA2(acc[j + 2][0][0], c2, mq0.x); FFMA2(acc[j + 2][0][1], c2, mq0.y);
                FFMA2(acc[j + 2][1][0], c2, mq1.x); FFMA2(acc[j + 2][1][1], c2, mq1.y);
                FFMA2(acc[j + 3][0][0], c3, mq0.x); FFMA2(acc[j + 3][0][1], c3, mq0.y);
                FFMA2(acc[j + 3][1][0], c3, mq1.x); FFMA2(acc[j + 3][1][1], c3, mq1.y);
            }
            mq0 = nq0; mq1 = nq1;
        }

        // epilogue: ReLU + STG.128
        float* ob = out + (size_t)b * O_ * HW_ + px;
#pragma unroll
        for (int j = 0; j < 16; j++) {
            float4* orow = reinterpret_cast<float4*>(ob + (size_t)(o0 + j) * HW_);
#pragma unroll
            for (int qd = 0; qd < 2; qd++) {
                ull a0 = acc[j][qd][0], a1 = acc[j][qd][1];
                float4 v = make_float4(
                    fmaxf(__uint_as_float((uint)(a0 & 0xffffffffu)), 0.f),
                    fmaxf(__uint_as_float((uint)(a0 >> 32)),         0.f),
                    fmaxf(__uint_as_float((uint)(a1 & 0xffffffffu)), 0.f),
                    fmaxf(__uint_as_float((uint)(a1 >> 32)),         0.f));
                orow[lane + qd * 32] = v;
            }
        }
    }
}

// ---------------- launcher ----------------------------------------------------
extern "C" void kernel_launch(void* const* d_in, const int* in_sizes, int n_in,
                              void* d_out, int out_size) {
    const float* feat   = (const float*)d_in[0];
    const float* mask   = (const float*)d_in[1];
    const float* conv_w = (const float*)d_in[2];
    const float* conv_b = (const float*)d_in[3];
    const float* gamma  = (const float*)d_in[4];
    const float* beta   = (const float*)d_in[5];
    float* out = (float*)d_out;

    kstats<<<dim3(KS_CHUNKS, B_), 352>>>(mask);
    kprep_a<<<B_, 256>>>(feat, conv_w);
    kprep_b<<<B_, 128>>>(conv_b, gamma, beta);
    kmain<<<KM_NBLK, 256>>>(mask, out);
}

// round 10
// speedup vs baseline: 1.1920x; 1.1920x over previous
#include <cuda_runtime.h>
#include <cstdint>

#define B_  8
#define C_  21
#define D_  64
#define O_  128
#define HW_ 65536
#define N_TOT (B_ * HW_)

typedef unsigned long long ull;
typedef unsigned int uint;

#define FFMA2(acc, a, b) asm("fma.rn.f32x2 %0, %1, %2, %0;" : "+l"(acc) : "l"(a), "l"(b))
#define FADD2(acc, a)    asm("add.rn.f32x2 %0, %0, %1;"     : "+l"(acc) : "l"(a))

// ---------------- device scratch ---------------------------------------------
#define KS_CHUNKS 74
#define NVAL 252                      // 231 triangle + 21 sums
__device__ float g_Gp[KS_CHUNKS * B_ * NVAL];   // per-block stat partials
__device__ float g_W2T[B_ * C_ * O_];           // combined weights [b][c][o]
__device__ float g_partY[B_ * O_];
__device__ float g_partQ[B_ * O_];
__device__ float g_A2s[B_ * C_ * O_];           // alpha*W2 (scalar), [b][c][o]
__device__ float g_bias2f[O_];                  // fused bias (scalar)

// ---------------- helpers ------------------------------------------------------
__device__ __forceinline__ void cp16(void* dst, const void* src) {
    uint s = (uint)__cvta_generic_to_shared(dst);
    asm volatile("cp.async.cg.shared.global [%0], [%1], 16;" :: "r"(s), "l"(src));
}
#define CP_COMMIT() asm volatile("cp.async.commit_group;" ::: "memory")
#define CP_WAIT1()  asm volatile("cp.async.wait_group 1;" ::: "memory")
#define CP_WAIT0()  asm volatile("cp.async.wait_group 0;" ::: "memory")

__device__ __forceinline__ float pairsum(ull a) {
    return __uint_as_float((uint)(a & 0xffffffffu)) + __uint_as_float((uint)(a >> 32));
}
__device__ __forceinline__ ull lo64(float4 v) {
    return ((ull)__float_as_uint(v.y) << 32) | __float_as_uint(v.x);
}
__device__ __forceinline__ ull hi64(float4 v) {
    return ((ull)__float_as_uint(v.w) << 32) | __float_as_uint(v.z);
}
__device__ __forceinline__ ull dup2(float x) {
    ull r;
    asm("mov.b64 %0, {%1, %1};" : "=l"(r) : "f"(x));
    return r;
}
__device__ __forceinline__ float wredsum(float v) {
#pragma unroll
    for (int off = 16; off; off >>= 1) v += __shfl_xor_sync(0xffffffffu, v, off);
    return v;
}

// ---------------- kstats: symmetric (triangular) Gram, LDG streaming ---------
// grid (74, 8), 352 threads = 11 warps. Warp w<10 owns row pair (w, 20-w);
// warp 10 owns row 10. Lower triangle only: 231 + 21 sums.
template <int LO, int HI>
__device__ __forceinline__ void gram_warp(const float* __restrict__ mb,
                                          int u0, int u1, int lane,
                                          float* __restrict__ gp) {
    constexpr bool SGL = (LO == HI);
    constexpr int TRI_LO = LO * (LO + 1) / 2;
    constexpr int TRI_HI = HI * (HI + 1) / 2;

    ull accH[HI + 1];
    ull accL[SGL ? 1 : LO + 1];
    ull sL = 0ull, sH = 0ull;
#pragma unroll
    for (int c = 0; c <= HI; c++) accH[c] = 0ull;
    if (!SGL) {
#pragma unroll
        for (int c = 0; c <= LO; c++) accL[c] = 0ull;
    }

#pragma unroll 1
    for (int u = u0; u < u1; u++) {
        const int q = u * 32 + lane;
        float4 vH = reinterpret_cast<const float4*>(mb + (size_t)HI * HW_)[q];
        ull mrHa = lo64(vH), mrHb = hi64(vH);
        FADD2(sH, mrHa); FADD2(sH, mrHb);
        ull mrLa = 0, mrLb = 0;
        if (!SGL) {
            float4 vL = reinterpret_cast<const float4*>(mb + (size_t)LO * HW_)[q];
            mrLa = lo64(vL); mrLb = hi64(vL);
            FADD2(sL, mrLa); FADD2(sL, mrLb);
        }
#pragma unroll
        for (int c = 0; c <= HI; c++) {
            ull va, vb;
            if (c == HI)              { va = mrHa; vb = mrHb; }
            else if (!SGL && c == LO) { va = mrLa; vb = mrLb; }
            else {
                float4 v = reinterpret_cast<const float4*>(mb + (size_t)c * HW_)[q];
                va = lo64(v); vb = hi64(v);
            }
            FFMA2(accH[c], mrHa, va);
            FFMA2(accH[c], mrHb, vb);
            if (!SGL && c <= LO) {
                FFMA2(accL[c], mrLa, va);
                FFMA2(accL[c], mrLb, vb);
            }
        }
    }

#pragma unroll
    for (int c = 0; c <= HI; c++) {
        float v = wredsum(pairsum(accH[c]));
        if (lane == 0) gp[TRI_HI + c] = v;
    }
    {
        float v = wredsum(pairsum(sH));
        if (lane == 0) gp[231 + HI] = v;
    }
    if (!SGL) {
#pragma unroll
        for (int c = 0; c <= LO; c++) {
            float v = wredsum(pairsum(accL[c]));
            if (lane == 0) gp[TRI_LO + c] = v;
        }
        float v = wredsum(pairsum(sL));
        if (lane == 0) gp[231 + LO] = v;
    }
}

__global__ __launch_bounds__(352) void kstats(const float* __restrict__ mask) {
    const int b = blockIdx.y;
    const int bidx = blockIdx.x;
    const int wid = threadIdx.x >> 5;
    const int lane = threadIdx.x & 31;

    const int u0 = (bidx * 512) / KS_CHUNKS;
    const int u1 = ((bidx + 1) * 512) / KS_CHUNKS;

    const float* mb = mask + (size_t)b * C_ * HW_;
    float* gp = g_Gp + (bidx * B_ + b) * NVAL;

    switch (wid) {
        case 0:  gram_warp<0, 20>(mb, u0, u1, lane, gp); break;
        case 1:  gram_warp<1, 19>(mb, u0, u1, lane, gp); break;
        case 2:  gram_warp<2, 18>(mb, u0, u1, lane, gp); break;
        case 3:  gram_warp<3, 17>(mb, u0, u1, lane, gp); break;
        case 4:  gram_warp<4, 16>(mb, u0, u1, lane, gp); break;
        case 5:  gram_warp<5, 15>(mb, u0, u1, lane, gp); break;
        case 6:  gram_warp<6, 14>(mb, u0, u1, lane, gp); break;
        case 7:  gram_warp<7, 13>(mb, u0, u1, lane, gp); break;
        case 8:  gram_warp<8, 12>(mb, u0, u1, lane, gp); break;
        case 9:  gram_warp<9, 11>(mb, u0, u1, lane, gp); break;
        default: gram_warp<10, 10>(mb, u0, u1, lane, gp); break;
    }
}

// ---------------- kprep_a: W2T + partial reduce + quadratic forms -------------
__global__ __launch_bounds__(256) void kprep_a(const float* __restrict__ feat,
                                               const float* __restrict__ conv_w) {
    __shared__ float sWT[D_ * 129 + 32];
    __shared__ float sF[C_ * D_];
    __shared__ float sG[231];
    __shared__ float sS[C_];
    const int b = blockIdx.x;
    const int tid = threadIdx.x;

    for (int i = tid; i < O_ * D_; i += 256) {
        int o = i >> 6, d = i & 63;
        sWT[d * 129 + o] = conv_w[i];
    }
    for (int i = tid; i < C_ * D_; i += 256) sF[i] = feat[b * C_ * D_ + i];
    for (int v = tid; v < NVAL; v += 256) {
        float s = 0.f;
#pragma unroll
        for (int ch = 0; ch < KS_CHUNKS; ch++) s += g_Gp[(ch * B_ + b) * NVAL + v];
        if (v < 231) sG[v] = s;
        else         sS[v - 231] = s;
    }
    __syncthreads();

    for (int idx = tid; idx < C_ * O_; idx += 256) {
        int c = idx >> 7, o = idx & 127;
        float s = 0.f;
#pragma unroll
        for (int d = 0; d < D_; d++)
            s = fmaf(sWT[d * 129 + o], sF[c * D_ + d], s);
        g_W2T[b * C_ * O_ + idx] = s;
    }
    __syncthreads();

    if (tid < O_) {
        const int o = tid;
        float w[C_];
#pragma unroll
        for (int c = 0; c < C_; c++) w[c] = g_W2T[(b * C_ + c) * O_ + o];
        float sumY = 0.f;
#pragma unroll
        for (int c = 0; c < C_; c++) sumY = fmaf(w[c], sS[c], sumY);
        float sumQ = 0.f;
#pragma unroll
        for (int r = 0; r < C_; r++) {
            const int tr = r * (r + 1) / 2;
            float t = sG[tr + r] * w[r];
#pragma unroll
            for (int c = 0; c < r; c++) t = fmaf(2.f * sG[tr + c], w[c], t);
            sumQ = fmaf(w[r], t, sumQ);
        }
        g_partY[b * O_ + o] = sumY;
        g_partQ[b * O_ + o] = sumQ;
    }
}

// ---------------- kprep_b: alpha/bias (redundant per block) + A2 scaling -----
__global__ __launch_bounds__(128) void kprep_b(const float* __restrict__ conv_b,
                                               const float* __restrict__ gamma,
                                               const float* __restrict__ beta) {
    const int b = blockIdx.x;
    const int o = threadIdx.x;

    float sumY = 0.f, sumQ = 0.f;
#pragma unroll
    for (int bb = 0; bb < B_; bb++) {
        sumY += g_partY[bb * O_ + o];
        sumQ += g_partQ[bb * O_ + o];
    }
    const float invN = 1.f / (float)N_TOT;
    const float b0 = conv_b[o];
    const float es = sumY * invN;
    const float mean = b0 + es;
    const float ey2 = sumQ * invN + 2.f * b0 * es + b0 * b0;
    const float var = ey2 - mean * mean;
    const float alpha = gamma[o] * rsqrtf(var + 1e-5f);

    if (b == 0) g_bias2f[o] = beta[o] + alpha * (b0 - mean);
#pragma unroll
    for (int c = 0; c < C_; c++) {
        const int idx = b * C_ * O_ + c * O_ + o;
        g_A2s[idx] = alpha * g_W2T[idx];
    }
}

// ---------------- kmain: 512-thread fused K=21 GEMM + BN + ReLU --------------
// 148 blocks x 512 threads (1 block/SM = 16 warps). Subtile = 256 px x 128 ch.
// Warp = 8 channels x 256 px; thread = 2 quads (8 px) x 8 ch -> acc 32 ull.
// Mask: cp.async double buffer (R8 sync pattern). Coefs: SCALAR in smem,
// uniform LDS.128 + ALU dup (mov.b64) -> halves coef wavefronts, cuts regs.
#define KM_NBLK 148
#define KM_NT   2048        // 8 b * 256 subtiles of 256 px
#define KM_PX   256

__global__ __launch_bounds__(512) void kmain(const float* __restrict__ mask,
                                             float* __restrict__ out) {
    __shared__ __align__(16) float sM[2][C_][KM_PX];   // 43008 B
    __shared__ __align__(16) float sCF[C_ * O_];       // 10752 B (scalar coefs)

    const int tid = threadIdx.x;
    const int wid = tid >> 5;
    const int lane = tid & 31;
    const int o0 = wid * 8;

    const int bid = blockIdx.x;
    const int t0 = (bid * KM_NT) / KM_NBLK;
    const int t1 = ((bid + 1) * KM_NT) / KM_NBLK;

    // fused bias: 8 scalar regs per thread (warp-uniform LDG, L1-hot)
    float biasv[8];
#pragma unroll
    for (int j = 0; j < 8; j++) biasv[j] = g_bias2f[o0 + j];

    auto issue = [&](int s, int buf) {
        const int b = s >> 8;
        const int px = (s & 255) * KM_PX;
        const float* mb = mask + (size_t)b * C_ * HW_ + px;
        for (int u = tid; u < C_ * (KM_PX / 4); u += 512) {   // 1344 16B units
            int c = u >> 6, q = u & 63;
            cp16(&sM[buf][c][q * 4], mb + (size_t)c * HW_ + q * 4);
        }
        CP_COMMIT();
    };
    auto stage = [&](int b) {
        const float* src = g_A2s + (size_t)b * C_ * O_;
        for (int i = tid; i < C_ * O_ / 4; i += 512)
            reinterpret_cast<float4*>(sCF)[i] = reinterpret_cast<const float4*>(src)[i];
    };

    int curb = t0 >> 8;
    issue(t0, 0);
    stage(curb);

#pragma unroll 1
    for (int s = t0; s < t1; s++) {
        const int buf = (s - t0) & 1;
        if (s + 1 < t1) { issue(s + 1, buf ^ 1); CP_WAIT1(); } else { CP_WAIT0(); }
        __syncthreads();
        const int b = s >> 8;
        if (b != curb) { stage(b); curb = b; __syncthreads(); }

        ull acc[8][2][2];   // [ch][quad][half]
#pragma unroll
        for (int j = 0; j < 8; j++) {
            ull d = dup2(biasv[j]);
            acc[j][0][0] = d; acc[j][0][1] = d;
            acc[j][1][0] = d; acc[j][1][1] = d;
        }

#pragma unroll
        for (int c = 0; c < C_; c++) {
            const float* smc = sM[buf][c];
            ulonglong2 mq0 = reinterpret_cast<const ulonglong2*>(smc)[lane];
            ulonglong2 mq1 = reinterpret_cast<const ulonglong2*>(smc)[lane + 32];
            // 8 scalar coefs: two warp-uniform LDS.128
            float4 w0 = *reinterpret_cast<const float4*>(&sCF[c * O_ + o0]);
            float4 w1 = *reinterpret_cast<const float4*>(&sCF[c * O_ + o0 + 4]);
            ull c0 = dup2(w0.x), c1 = dup2(w0.y), c2 = dup2(w0.z), c3 = dup2(w0.w);
            ull c4 = dup2(w1.x), c5 = dup2(w1.y), c6 = dup2(w1.z), c7 = dup2(w1.w);
            FFMA2(acc[0][0][0], c0, mq0.x); FFMA2(acc[0][0][1], c0, mq0.y);
            FFMA2(acc[0][1][0], c0, mq1.x); FFMA2(acc[0][1][1], c0, mq1.y);
            FFMA2(acc[1][0][0], c1, mq0.x); FFMA2(acc[1][0][1], c1, mq0.y);
            FFMA2(acc[1][1][0], c1, mq1.x); FFMA2(acc[1][1][1], c1, mq1.y);
            FFMA2(acc[2][0][0], c2, mq0.x); FFMA2(acc[2][0][1], c2, mq0.y);
            FFMA2(acc[2][1][0], c2, mq1.x); FFMA2(acc[2][1][1], c2, mq1.y);
            FFMA2(acc[3][0][0], c3, mq0.x); FFMA2(acc[3][0][1], c3, mq0.y);
            FFMA2(acc[3][1][0], c3, mq1.x); FFMA2(acc[3][1][1], c3, mq1.y);
            FFMA2(acc[4][0][0], c4, mq0.x); FFMA2(acc[4][0][1], c4, mq0.y);
            FFMA2(acc[4][1][0], c4, mq1.x); FFMA2(acc[4][1][1], c4, mq1.y);
            FFMA2(acc[5][0][0], c5, mq0.x); FFMA2(acc[5][0][1], c5, mq0.y);
            FFMA2(acc[5][1][0], c5, mq1.x); FFMA2(acc[5][1][1], c5, mq1.y);
            FFMA2(acc[6][0][0], c6, mq0.x); FFMA2(acc[6][0][1], c6, mq0.y);
            FFMA2(acc[6][1][0], c6, mq1.x); FFMA2(acc[6][1][1], c6, mq1.y);
            FFMA2(acc[7][0][0], c7, mq0.x); FFMA2(acc[7][0][1], c7, mq0.y);
            FFMA2(acc[7][1][0], c7, mq1.x); FFMA2(acc[7][1][1], c7, mq1.y);
        }
        __syncthreads();   // all reads of sM[buf]/sCF done before refill

        // epilogue: ReLU + STG.128
        const int px = (s & 255) * KM_PX;
        float* ob = out + (size_t)b * O_ * HW_ + px;
#pragma unroll
        for (int j = 0; j < 8; j++) {
            float4* orow = reinterpret_cast<float4*>(ob + (size_t)(o0 + j) * HW_);
#pragma unroll
            for (int qd = 0; qd < 2; qd++) {
                ull a0 = acc[j][qd][0], a1 = acc[j][qd][1];
                float4 v = make_float4(
                    fmaxf(__uint_as_float((uint)(a0 & 0xffffffffu)), 0.f),
                    fmaxf(__uint_as_float((uint)(a0 >> 32)),         0.f),
                    fmaxf(__uint_as_float((uint)(a1 & 0xffffffffu)), 0.f),
                    fmaxf(__uint_as_float((uint)(a1 >> 32)),         0.f));
                orow[lane + qd * 32] = v;
            }
        }
    }
}

// ---------------- launcher ----------------------------------------------------
extern "C" void kernel_launch(void* const* d_in, const int* in_sizes, int n_in,
                              void* d_out, int out_size) {
    const float* feat   = (const float*)d_in[0];
    const float* mask   = (const float*)d_in[1];
    const float* conv_w = (const float*)d_in[2];
    const float* conv_b = (const float*)d_in[3];
    const float* gamma  = (const float*)d_in[4];
    const float* beta   = (const float*)d_in[5];
    float* out = (float*)d_out;

    kstats<<<dim3(KS_CHUNKS, B_), 352>>>(mask);
    kprep_a<<<B_, 256>>>(feat, conv_w);
    kprep_b<<<B_, 128>>>(conv_b, gamma, beta);
    kmain<<<KM_NBLK, 512>>>(mask, out);
}